// round 16
// baseline (speedup 1.0000x reference)
#include <cuda_runtime.h>
#include <cuda_fp16.h>
#include <cstdint>

#define NN 100000
#define NE 1600000
#define IND 128
#define HID 32
#define OUTD 64
#define NCOL 288   // 8*32 + 32 (root)

// layer-2 32-bit fixed point: lane = deg*2^24 + round(v*16384)
#define QSCALE 16384.0f
#define QINV   (1.0f / 16384.0f)
#define QBIAS  (1u << 24)

// -------- scratch (static device memory; 16B-aligned) --------
__device__ __align__(16) __half g_wcatT[NCOL * IND];            // fp16 weights, transposed [j][k]
__device__ __align__(16) __half g_xh[(size_t)NN * IND];         // fp16 x (25.6 MB)
__device__ __align__(16) __half g_y1h[(size_t)NN * NCOL];       // fp16 y1 (57 MB)
__device__ __align__(16) __half g_agg1h[NN * HID];              // fp16 accumulators (6.4 MB)
__device__ __align__(16) unsigned long long g_acc2q[NN];        // 32-bit×2 lanes
__device__ __align__(16) int g_degi[NN];
__device__ __align__(16) float g_h[NN * HID];
__device__ __align__(16) float g_y2[NN * 16];                   // [n][r][c]: h @ W2p
__device__ __align__(16) uint2 g_epk[NE];                       // {src, dst | rel<<20} (12.8 MB)
__device__ __align__(16) float g_W2p[512];
__device__ __align__(16) float g_r2p[64];
__device__ __align__(16) float g_bp[2];
__device__ int g_is64;

__global__ void detect_kernel(const int* __restrict__ ei_raw) {
    if (threadIdx.x == 0 && blockIdx.x == 0) {
        int is64 = 1;
        for (int i = 0; i < 1024; i++)
            if (ei_raw[2 * i + 1] != 0) { is64 = 0; break; }
        g_is64 = is64;
    }
}

__device__ __forceinline__ int edge_at(const void* __restrict__ p, size_t i) {
    if (g_is64) return (int)((const long long*)p)[i];
    return ((const int*)p)[i];
}

// -------- prep: pack fp16 transposed weights, fold classifier --------
__global__ void prep_kernel(const float* __restrict__ W1, const float* __restrict__ root1,
                            const float* __restrict__ W2, const float* __restrict__ root2,
                            const float* __restrict__ b2, const float* __restrict__ lin_w,
                            const float* __restrict__ lin_b) {
    int t = blockIdx.x * blockDim.x + threadIdx.x;
    int stride = gridDim.x * blockDim.x;
    for (int i = t; i < NCOL * IND; i += stride) {
        int j = i / IND, k = i % IND;
        float v;
        if (j < 256) v = W1[(j >> 5) * (IND * HID) + k * HID + (j & 31)];
        else         v = root1[k * HID + (j - 256)];
        g_wcatT[i] = __float2half(v);
    }
    if (t < 512) {
        int idx = t >> 1, c = t & 1;
        const float* wrow = W2 + idx * OUTD;
        float s = 0.f;
        for (int o = 0; o < OUTD; o++) s += wrow[o] * lin_w[o * 2 + c];
        g_W2p[t] = s;
    }
    if (t < 64) {
        int k = t >> 1, c = t & 1;
        float s = 0.f;
        for (int o = 0; o < OUTD; o++) s += root2[k * OUTD + o] * lin_w[o * 2 + c];
        g_r2p[t] = s;
    }
    if (t < 2) {
        float s = lin_b[t];
        for (int o = 0; o < OUTD; o++) s += b2[o] * lin_w[o * 2 + t];
        g_bp[t] = s;
    }
}

// -------- stage x to fp16 (critical path: feeds gemm) --------
__global__ void stage_kernel(const float* __restrict__ x) {
    int t = blockIdx.x * blockDim.x + threadIdx.x;
    int stride = gridDim.x * blockDim.x;
    __half2* xh2 = (__half2*)g_xh;
    for (int i = t; i < NN * 32; i += stride) {
        float4 v = ((const float4*)x)[i];
        xh2[i * 2 + 0] = __floats2half2_rn(v.x, v.y);
        xh2[i * 2 + 1] = __floats2half2_rn(v.z, v.w);
    }
}

// -------- side stream: zero accumulators --------
__global__ void zero_kernel() {
    int t = blockIdx.x * blockDim.x + threadIdx.x;
    int stride = gridDim.x * blockDim.x;
    float4 z = make_float4(0.f, 0.f, 0.f, 0.f);
    for (int i = t; i < NN * 4; i += stride)  ((float4*)g_agg1h)[i] = z;
    for (int i = t; i < NN / 2; i += stride)  ((float4*)g_acc2q)[i] = z;
    for (int i = t; i < NN / 4; i += stride)  ((float4*)g_degi)[i]  = z;
}

// -------- side stream: pack edges + degree histogram --------
__global__ __launch_bounds__(256) void pack_kernel(const void* __restrict__ ei,
                                                   const void* __restrict__ et) {
    int e = blockIdx.x * 256 + threadIdx.x;   // NE threads exactly
    int src = edge_at(ei, e);
    int dst = edge_at(ei, (size_t)NE + e);
    int r   = edge_at(et, e);
    g_epk[e] = make_uint2((unsigned)src, (unsigned)dst | ((unsigned)r << 20));
    atomicAdd(&g_degi[dst], 1);
}

// -------- fp16 tensor-core GEMM (cp.async double-buffered) --------
#define GBM 128
#define GBN 96
#define GBK 64
#define A_STRH 72
#define B_STRH 72
#define A_TILE_H (GBM * A_STRH)
#define B_TILE_H (GBN * B_STRH)
#define GEMM_SMEM ((2 * A_TILE_H + 2 * B_TILE_H) * 2)

__device__ __forceinline__ void cpa16(uint32_t dst_s, const void* src, int sz) {
    asm volatile("cp.async.ca.shared.global [%0], [%1], 16, %2;\n"
                 :: "r"(dst_s), "l"(src), "r"(sz));
}

__global__ __launch_bounds__(256) void gemm_f16_kernel() {
    extern __shared__ __half smem[];
    uint32_t smem_base = (uint32_t)__cvta_generic_to_shared(smem);
    uint32_t bs_base = smem_base + 2 * A_TILE_H * 2;

    int tid  = threadIdx.x;
    int lane = tid & 31, wid = tid >> 5;
    int warp_m = wid & 3, warp_n = wid >> 2;
    int br = blockIdx.x * GBM;
    int bc = blockIdx.y * GBN;
    int gID = lane >> 2, tig = lane & 3;

    float c[2][6][4];
#pragma unroll
    for (int mt = 0; mt < 2; mt++)
#pragma unroll
        for (int nt = 0; nt < 6; nt++)
#pragma unroll
            for (int q = 0; q < 4; q++) c[mt][nt][q] = 0.f;

    auto load_stage = [&](int s, int k0) {
        uint32_t a_base = smem_base + (uint32_t)s * A_TILE_H * 2;
        uint32_t b_base = bs_base + (uint32_t)s * B_TILE_H * 2;
#pragma unroll
        for (int j = 0; j < 4; j++) {
            int cch = tid + j * 256;
            int row = cch >> 3, kc = cch & 7;
            int gr = br + row;
            const __half* src = g_xh + (size_t)(gr < NN ? gr : 0) * IND + k0 + kc * 8;
            cpa16(a_base + (row * A_STRH + kc * 8) * 2, src, gr < NN ? 16 : 0);
        }
#pragma unroll
        for (int j = 0; j < 3; j++) {
            int cch = tid + j * 256;
            int row = cch >> 3, kc = cch & 7;
            const __half* src = g_wcatT + (bc + row) * IND + k0 + kc * 8;
            cpa16(b_base + (row * B_STRH + kc * 8) * 2, src, 16);
        }
    };

    load_stage(0, 0);
    asm volatile("cp.async.commit_group;\n");

#pragma unroll
    for (int it = 0; it < 2; it++) {
        if (it < 1) {
            load_stage(1, GBK);
            asm volatile("cp.async.commit_group;\n");
            asm volatile("cp.async.wait_group 1;\n");
        } else {
            asm volatile("cp.async.wait_group 0;\n");
        }
        __syncthreads();

        const uint32_t* Ac = (const uint32_t*)(smem + (it & 1) * A_TILE_H);
        const uint32_t* Bc = (const uint32_t*)(smem + 2 * A_TILE_H + (it & 1) * B_TILE_H);
#pragma unroll
        for (int ks = 0; ks < 4; ks++) {
            int kw = ks * 8;
            uint32_t a[2][4];
#pragma unroll
            for (int mt = 0; mt < 2; mt++) {
                int r0 = warp_m * 32 + mt * 16 + gID;
                a[mt][0] = Ac[r0 * 36 + kw + tig];
                a[mt][1] = Ac[(r0 + 8) * 36 + kw + tig];
                a[mt][2] = Ac[r0 * 36 + kw + 4 + tig];
                a[mt][3] = Ac[(r0 + 8) * 36 + kw + 4 + tig];
            }
            uint32_t b[6][2];
#pragma unroll
            for (int nt = 0; nt < 6; nt++) {
                int col = warp_n * 48 + nt * 8 + gID;
                b[nt][0] = Bc[col * 36 + kw + tig];
                b[nt][1] = Bc[col * 36 + kw + 4 + tig];
            }
#pragma unroll
            for (int mt = 0; mt < 2; mt++)
#pragma unroll
                for (int nt = 0; nt < 6; nt++)
                    asm volatile(
                        "mma.sync.aligned.m16n8k16.row.col.f32.f16.f16.f32 "
                        "{%0,%1,%2,%3}, {%4,%5,%6,%7}, {%8,%9}, {%0,%1,%2,%3};"
                        : "+f"(c[mt][nt][0]), "+f"(c[mt][nt][1]),
                          "+f"(c[mt][nt][2]), "+f"(c[mt][nt][3])
                        : "r"(a[mt][0]), "r"(a[mt][1]), "r"(a[mt][2]), "r"(a[mt][3]),
                          "r"(b[nt][0]), "r"(b[nt][1]));
        }
        __syncthreads();
    }

#pragma unroll
    for (int mt = 0; mt < 2; mt++) {
        int row0 = br + warp_m * 32 + mt * 16 + gID;
#pragma unroll
        for (int nt = 0; nt < 6; nt++) {
            int col = bc + warp_n * 48 + nt * 8 + 2 * tig;
            if (row0 < NN)
                *(__half2*)&g_y1h[(size_t)row0 * NCOL + col] =
                    __floats2half2_rn(c[mt][nt][0], c[mt][nt][1]);
            if (row0 + 8 < NN)
                *(__half2*)&g_y1h[(size_t)(row0 + 8) * NCOL + col] =
                    __floats2half2_rn(c[mt][nt][2], c[mt][nt][3]);
        }
    }
}

// -------- layer-1 scatter: packed index + LDG.128 gather + red.v4.f16x2, no deg --------
__global__ __launch_bounds__(256) void scatter1_kernel() {
    int t = blockIdx.x * blockDim.x + threadIdx.x;   // NE*4 threads exactly
    int e = t >> 2, c = t & 3;
    uint2 pk = g_epk[e];
    int src = (int)pk.x;
    int dst = (int)(pk.y & 0xFFFFF);
    int r   = (int)(pk.y >> 20);
    uint4 v = *(const uint4*)&g_y1h[(size_t)src * NCOL + r * HID + c * 8];
    asm volatile("red.global.add.noftz.v4.f16x2 [%0], {%1,%2,%3,%4};"
                 :: "l"(&g_agg1h[dst * HID + c * 8]),
                    "r"(v.x), "r"(v.y), "r"(v.z), "r"(v.w) : "memory");
}

// -------- h = relu(agg1/deg + x@root1 + b1);  y2[n,r,:] = h[n] @ W2p[r] --------
__global__ __launch_bounds__(256) void h_y2_kernel(const float* __restrict__ b1) {
    __shared__ float sh[32][33];
    __shared__ float sw[512];
    int t = threadIdx.x;
    int n0 = blockIdx.x * 32;
    sw[t] = g_W2p[t];
    sw[t + 256] = g_W2p[t + 256];
#pragma unroll
    for (int j = 0; j < 4; j++) {
        int i = t + j * 256;
        int n_l = i >> 5, k = i & 31;
        int n = n0 + n_l;
        int di = g_degi[n];
        float sum = __half2float(g_agg1h[n * 32 + k]);
        float d = di > 1 ? (float)di : 1.f;
        float v = sum / d + __half2float(g_y1h[(size_t)n * NCOL + 256 + k]) + b1[k];
        v = v > 0.f ? v : 0.f;
        g_h[n * 32 + k] = v;
        sh[n_l][k] = v;
    }
    __syncthreads();
    int n_l = t >> 3, r = t & 7;
    float c0 = 0.f, c1 = 0.f;
#pragma unroll
    for (int k = 0; k < 32; k++) {
        float hv = sh[n_l][k];
        float2 w = *(const float2*)&sw[(r * 32 + k) * 2];
        c0 += hv * w.x;
        c1 += hv * w.y;
    }
    *(float2*)&g_y2[(n0 + n_l) * 16 + r * 2] = make_float2(c0, c1);
}

// -------- layer-2 scatter: packed index, one u64 atomic per edge --------
__global__ __launch_bounds__(256) void scatter2_kernel() {
    int e = blockIdx.x * blockDim.x + threadIdx.x;   // NE threads exactly
    uint2 pk = g_epk[e];
    int src = (int)pk.x;
    int dst = (int)(pk.y & 0xFFFFF);
    int r   = (int)(pk.y >> 20);
    float2 v = *(const float2*)&g_y2[src * 16 + r * 2];
    unsigned q0 = (unsigned)__float2int_rn(v.x * QSCALE) + QBIAS;
    unsigned q1 = (unsigned)__float2int_rn(v.y * QSCALE) + QBIAS;
    atomicAdd(&g_acc2q[dst], (unsigned long long)q0 | ((unsigned long long)q1 << 32));
}

// -------- out[n] = acc2[n]/deg + h[n] @ r2p + bp --------
__global__ __launch_bounds__(256) void out2_kernel(float* __restrict__ out) {
    int n = blockIdx.x * 256 + threadIdx.x;
    if (n >= NN) return;
    int di = g_degi[n];
    unsigned long long p = g_acc2q[n];
    float m0 = (float)(int)((unsigned)p - (unsigned)di * QBIAS) * QINV;
    float m1 = (float)(int)((unsigned)(p >> 32) - (unsigned)di * QBIAS) * QINV;
    float d = di > 1 ? (float)di : 1.f;
    float inv = 1.f / d;
    float c0 = m0 * inv;
    float c1 = m1 * inv;
#pragma unroll
    for (int k = 0; k < 32; k++) {
        float hv = g_h[n * 32 + k];
        c0 += hv * g_r2p[k * 2 + 0];
        c1 += hv * g_r2p[k * 2 + 1];
    }
    out[n * 2 + 0] = c0 + g_bp[0];
    out[n * 2 + 1] = c1 + g_bp[1];
}

extern "C" void kernel_launch(void* const* d_in, const int* in_sizes, int n_in,
                              void* d_out, int out_size) {
    const float* x     = (const float*)d_in[0];
    const void*  ei    = d_in[1];
    const void*  et    = d_in[2];
    const float* W1    = (const float*)d_in[3];
    const float* root1 = (const float*)d_in[4];
    const float* b1    = (const float*)d_in[5];
    const float* W2    = (const float*)d_in[6];
    const float* root2 = (const float*)d_in[7];
    const float* b2    = (const float*)d_in[8];
    const float* lin_w = (const float*)d_in[9];
    const float* lin_b = (const float*)d_in[10];
    float* out         = (float*)d_out;

    cudaFuncSetAttribute(gemm_f16_kernel,
                         cudaFuncAttributeMaxDynamicSharedMemorySize, GEMM_SMEM);

    cudaStream_t s1;
    cudaStreamCreateWithFlags(&s1, cudaStreamNonBlocking);
    cudaEvent_t evA, evB;
    cudaEventCreateWithFlags(&evA, cudaEventDisableTiming);
    cudaEventCreateWithFlags(&evB, cudaEventDisableTiming);

    detect_kernel<<<1, 32>>>((const int*)ei);

    // fork: side stream does accumulator zeroing + edge pack + deg histogram
    cudaEventRecord(evA, 0);
    cudaStreamWaitEvent(s1, evA, 0);
    zero_kernel<<<1024, 256, 0, s1>>>();
    pack_kernel<<<NE / 256, 256, 0, s1>>>(ei, et);
    cudaEventRecord(evB, s1);

    // main stream: weight prep + x staging + GEMM (independent of side stream)
    prep_kernel<<<145, 256>>>(W1, root1, W2, root2, b2, lin_w, lin_b);
    stage_kernel<<<2048, 256>>>(x);
    gemm_f16_kernel<<<dim3((NN + GBM - 1) / GBM, NCOL / GBN), 256, GEMM_SMEM>>>();

    // join, then the edge phase
    cudaStreamWaitEvent(0, evB, 0);
    scatter1_kernel<<<(NE * 4) / 256, 256>>>();
    h_y2_kernel<<<NN / 32, 256>>>(b1);
    scatter2_kernel<<<NE / 256, 256>>>();
    out2_kernel<<<(NN + 255) / 256, 256>>>(out);
}

// round 17
// speedup vs baseline: 1.3818x; 1.3818x over previous
#include <cuda_runtime.h>
#include <cuda_fp16.h>
#include <cstdint>

#define NN 100000
#define NE 1600000
#define IND 128
#define HID 32
#define OUTD 64
#define NCOL 288   // 8*32 + 32 (root)

// layer-2 32-bit fixed point: lane = deg*2^24 + round(v*16384)
#define QSCALE 16384.0f
#define QINV   (1.0f / 16384.0f)
#define QBIAS  (1u << 24)

// -------- scratch (static device memory; 16B-aligned) --------
__device__ __align__(16) __half g_wcatT[NCOL * IND];            // fp16 weights, transposed [j][k]
__device__ __align__(16) __half g_xh[(size_t)NN * IND];         // fp16 x (25.6 MB)
__device__ __align__(16) __half g_y1h[(size_t)NN * NCOL];       // fp16 y1 (57 MB)
__device__ __align__(16) __half g_agg1h[NN * HID];              // fp16 accumulators (6.4 MB)
__device__ __align__(16) unsigned long long g_acc2q[NN];        // 32-bit×2 lanes
__device__ __align__(16) int g_degi[NN];
__device__ __align__(16) float g_h[NN * HID];
__device__ __align__(16) float g_y2[NN * 16];                   // [n][r][c]: h @ W2p
__device__ __align__(16) uint2 g_epk[NE];                       // {src, dst | rel<<20} (12.8 MB)
__device__ __align__(16) float g_W2p[512];
__device__ __align__(16) float g_r2p[64];
__device__ __align__(16) float g_bp[2];
__device__ int g_is64;

__global__ void detect_kernel(const int* __restrict__ ei_raw) {
    if (threadIdx.x == 0 && blockIdx.x == 0) {
        int is64 = 1;
        for (int i = 0; i < 1024; i++)
            if (ei_raw[2 * i + 1] != 0) { is64 = 0; break; }
        g_is64 = is64;
    }
}

__device__ __forceinline__ int edge_at(const void* __restrict__ p, size_t i) {
    if (g_is64) return (int)((const long long*)p)[i];
    return ((const int*)p)[i];
}

// -------- prep: pack fp16 transposed weights, fold classifier --------
__global__ void prep_kernel(const float* __restrict__ W1, const float* __restrict__ root1,
                            const float* __restrict__ W2, const float* __restrict__ root2,
                            const float* __restrict__ b2, const float* __restrict__ lin_w,
                            const float* __restrict__ lin_b) {
    int t = blockIdx.x * blockDim.x + threadIdx.x;
    int stride = gridDim.x * blockDim.x;
    for (int i = t; i < NCOL * IND; i += stride) {
        int j = i / IND, k = i % IND;
        float v;
        if (j < 256) v = W1[(j >> 5) * (IND * HID) + k * HID + (j & 31)];
        else         v = root1[k * HID + (j - 256)];
        g_wcatT[i] = __float2half(v);
    }
    if (t < 512) {
        int idx = t >> 1, c = t & 1;
        const float* wrow = W2 + idx * OUTD;
        float s = 0.f;
        for (int o = 0; o < OUTD; o++) s += wrow[o] * lin_w[o * 2 + c];
        g_W2p[t] = s;
    }
    if (t < 64) {
        int k = t >> 1, c = t & 1;
        float s = 0.f;
        for (int o = 0; o < OUTD; o++) s += root2[k * OUTD + o] * lin_w[o * 2 + c];
        g_r2p[t] = s;
    }
    if (t < 2) {
        float s = lin_b[t];
        for (int o = 0; o < OUTD; o++) s += b2[o] * lin_w[o * 2 + t];
        g_bp[t] = s;
    }
}

// -------- fused: zero accumulators + stage x to fp16 --------
__global__ void zero_kernel(const float* __restrict__ x) {
    int t = blockIdx.x * blockDim.x + threadIdx.x;
    int stride = gridDim.x * blockDim.x;
    float4 z = make_float4(0.f, 0.f, 0.f, 0.f);
    for (int i = t; i < NN * 4; i += stride)  ((float4*)g_agg1h)[i] = z;
    for (int i = t; i < NN / 2; i += stride)  ((float4*)g_acc2q)[i] = z;
    for (int i = t; i < NN / 4; i += stride)  ((float4*)g_degi)[i]  = z;
    __half2* xh2 = (__half2*)g_xh;
    for (int i = t; i < NN * 32; i += stride) {
        float4 v = ((const float4*)x)[i];
        xh2[i * 2 + 0] = __floats2half2_rn(v.x, v.y);
        xh2[i * 2 + 1] = __floats2half2_rn(v.z, v.w);
    }
}

// -------- pack edges + degree histogram (after zero) --------
__global__ __launch_bounds__(256) void pack_kernel(const void* __restrict__ ei,
                                                   const void* __restrict__ et) {
    int e = blockIdx.x * 256 + threadIdx.x;   // NE threads exactly
    int src = edge_at(ei, e);
    int dst = edge_at(ei, (size_t)NE + e);
    int r   = edge_at(et, e);
    g_epk[e] = make_uint2((unsigned)src, (unsigned)dst | ((unsigned)r << 20));
    atomicAdd(&g_degi[dst], 1);
}

// -------- fp16 tensor-core GEMM (cp.async double-buffered) --------
#define GBM 128
#define GBN 96
#define GBK 64
#define A_STRH 72
#define B_STRH 72
#define A_TILE_H (GBM * A_STRH)
#define B_TILE_H (GBN * B_STRH)
#define GEMM_SMEM ((2 * A_TILE_H + 2 * B_TILE_H) * 2)

__device__ __forceinline__ void cpa16(uint32_t dst_s, const void* src, int sz) {
    asm volatile("cp.async.ca.shared.global [%0], [%1], 16, %2;\n"
                 :: "r"(dst_s), "l"(src), "r"(sz));
}

__global__ __launch_bounds__(256) void gemm_f16_kernel() {
    extern __shared__ __half smem[];
    uint32_t smem_base = (uint32_t)__cvta_generic_to_shared(smem);
    uint32_t bs_base = smem_base + 2 * A_TILE_H * 2;

    int tid  = threadIdx.x;
    int lane = tid & 31, wid = tid >> 5;
    int warp_m = wid & 3, warp_n = wid >> 2;
    int br = blockIdx.x * GBM;
    int bc = blockIdx.y * GBN;
    int gID = lane >> 2, tig = lane & 3;

    float c[2][6][4];
#pragma unroll
    for (int mt = 0; mt < 2; mt++)
#pragma unroll
        for (int nt = 0; nt < 6; nt++)
#pragma unroll
            for (int q = 0; q < 4; q++) c[mt][nt][q] = 0.f;

    auto load_stage = [&](int s, int k0) {
        uint32_t a_base = smem_base + (uint32_t)s * A_TILE_H * 2;
        uint32_t b_base = bs_base + (uint32_t)s * B_TILE_H * 2;
#pragma unroll
        for (int j = 0; j < 4; j++) {
            int cch = tid + j * 256;
            int row = cch >> 3, kc = cch & 7;
            int gr = br + row;
            const __half* src = g_xh + (size_t)(gr < NN ? gr : 0) * IND + k0 + kc * 8;
            cpa16(a_base + (row * A_STRH + kc * 8) * 2, src, gr < NN ? 16 : 0);
        }
#pragma unroll
        for (int j = 0; j < 3; j++) {
            int cch = tid + j * 256;
            int row = cch >> 3, kc = cch & 7;
            const __half* src = g_wcatT + (bc + row) * IND + k0 + kc * 8;
            cpa16(b_base + (row * B_STRH + kc * 8) * 2, src, 16);
        }
    };

    load_stage(0, 0);
    asm volatile("cp.async.commit_group;\n");

#pragma unroll
    for (int it = 0; it < 2; it++) {
        if (it < 1) {
            load_stage(1, GBK);
            asm volatile("cp.async.commit_group;\n");
            asm volatile("cp.async.wait_group 1;\n");
        } else {
            asm volatile("cp.async.wait_group 0;\n");
        }
        __syncthreads();

        const uint32_t* Ac = (const uint32_t*)(smem + (it & 1) * A_TILE_H);
        const uint32_t* Bc = (const uint32_t*)(smem + 2 * A_TILE_H + (it & 1) * B_TILE_H);
#pragma unroll
        for (int ks = 0; ks < 4; ks++) {
            int kw = ks * 8;
            uint32_t a[2][4];
#pragma unroll
            for (int mt = 0; mt < 2; mt++) {
                int r0 = warp_m * 32 + mt * 16 + gID;
                a[mt][0] = Ac[r0 * 36 + kw + tig];
                a[mt][1] = Ac[(r0 + 8) * 36 + kw + tig];
                a[mt][2] = Ac[r0 * 36 + kw + 4 + tig];
                a[mt][3] = Ac[(r0 + 8) * 36 + kw + 4 + tig];
            }
            uint32_t b[6][2];
#pragma unroll
            for (int nt = 0; nt < 6; nt++) {
                int col = warp_n * 48 + nt * 8 + gID;
                b[nt][0] = Bc[col * 36 + kw + tig];
                b[nt][1] = Bc[col * 36 + kw + 4 + tig];
            }
#pragma unroll
            for (int mt = 0; mt < 2; mt++)
#pragma unroll
                for (int nt = 0; nt < 6; nt++)
                    asm volatile(
                        "mma.sync.aligned.m16n8k16.row.col.f32.f16.f16.f32 "
                        "{%0,%1,%2,%3}, {%4,%5,%6,%7}, {%8,%9}, {%0,%1,%2,%3};"
                        : "+f"(c[mt][nt][0]), "+f"(c[mt][nt][1]),
                          "+f"(c[mt][nt][2]), "+f"(c[mt][nt][3])
                        : "r"(a[mt][0]), "r"(a[mt][1]), "r"(a[mt][2]), "r"(a[mt][3]),
                          "r"(b[nt][0]), "r"(b[nt][1]));
        }
        __syncthreads();
    }

#pragma unroll
    for (int mt = 0; mt < 2; mt++) {
        int row0 = br + warp_m * 32 + mt * 16 + gID;
#pragma unroll
        for (int nt = 0; nt < 6; nt++) {
            int col = bc + warp_n * 48 + nt * 8 + 2 * tig;
            if (row0 < NN)
                *(__half2*)&g_y1h[(size_t)row0 * NCOL + col] =
                    __floats2half2_rn(c[mt][nt][0], c[mt][nt][1]);
            if (row0 + 8 < NN)
                *(__half2*)&g_y1h[(size_t)(row0 + 8) * NCOL + col] =
                    __floats2half2_rn(c[mt][nt][2], c[mt][nt][3]);
        }
    }
}

// -------- layer-1 scatter: packed index + LDG.128 gather + red.v4.f16x2, no deg --------
__global__ __launch_bounds__(256) void scatter1_kernel() {
    int t = blockIdx.x * blockDim.x + threadIdx.x;   // NE*4 threads exactly
    int e = t >> 2, c = t & 3;
    uint2 pk = g_epk[e];
    int src = (int)pk.x;
    int dst = (int)(pk.y & 0xFFFFF);
    int r   = (int)(pk.y >> 20);
    uint4 v = *(const uint4*)&g_y1h[(size_t)src * NCOL + r * HID + c * 8];
    asm volatile("red.global.add.noftz.v4.f16x2 [%0], {%1,%2,%3,%4};"
                 :: "l"(&g_agg1h[dst * HID + c * 8]),
                    "r"(v.x), "r"(v.y), "r"(v.z), "r"(v.w) : "memory");
}

// -------- h = relu(agg1/deg + x@root1 + b1);  y2[n,r,:] = h[n] @ W2p[r] --------
__global__ __launch_bounds__(256) void h_y2_kernel(const float* __restrict__ b1) {
    __shared__ float sh[32][33];
    __shared__ float sw[512];
    int t = threadIdx.x;
    int n0 = blockIdx.x * 32;
    sw[t] = g_W2p[t];
    sw[t + 256] = g_W2p[t + 256];
#pragma unroll
    for (int j = 0; j < 4; j++) {
        int i = t + j * 256;
        int n_l = i >> 5, k = i & 31;
        int n = n0 + n_l;
        int di = g_degi[n];
        float sum = __half2float(g_agg1h[n * 32 + k]);
        float d = di > 1 ? (float)di : 1.f;
        float v = sum / d + __half2float(g_y1h[(size_t)n * NCOL + 256 + k]) + b1[k];
        v = v > 0.f ? v : 0.f;
        g_h[n * 32 + k] = v;
        sh[n_l][k] = v;
    }
    __syncthreads();
    int n_l = t >> 3, r = t & 7;
    float c0 = 0.f, c1 = 0.f;
#pragma unroll
    for (int k = 0; k < 32; k++) {
        float hv = sh[n_l][k];
        float2 w = *(const float2*)&sw[(r * 32 + k) * 2];
        c0 += hv * w.x;
        c1 += hv * w.y;
    }
    *(float2*)&g_y2[(n0 + n_l) * 16 + r * 2] = make_float2(c0, c1);
}

// -------- layer-2 scatter: packed index, one u64 atomic per edge --------
__global__ __launch_bounds__(256) void scatter2_kernel() {
    int e = blockIdx.x * blockDim.x + threadIdx.x;   // NE threads exactly
    uint2 pk = g_epk[e];
    int src = (int)pk.x;
    int dst = (int)(pk.y & 0xFFFFF);
    int r   = (int)(pk.y >> 20);
    float2 v = *(const float2*)&g_y2[src * 16 + r * 2];
    unsigned q0 = (unsigned)__float2int_rn(v.x * QSCALE) + QBIAS;
    unsigned q1 = (unsigned)__float2int_rn(v.y * QSCALE) + QBIAS;
    atomicAdd(&g_acc2q[dst], (unsigned long long)q0 | ((unsigned long long)q1 << 32));
}

// -------- out[n] = acc2[n]/deg + h[n] @ r2p + bp --------
__global__ __launch_bounds__(256) void out2_kernel(float* __restrict__ out) {
    int n = blockIdx.x * 256 + threadIdx.x;
    if (n >= NN) return;
    int di = g_degi[n];
    unsigned long long p = g_acc2q[n];
    float m0 = (float)(int)((unsigned)p - (unsigned)di * QBIAS) * QINV;
    float m1 = (float)(int)((unsigned)(p >> 32) - (unsigned)di * QBIAS) * QINV;
    float d = di > 1 ? (float)di : 1.f;
    float inv = 1.f / d;
    float c0 = m0 * inv;
    float c1 = m1 * inv;
#pragma unroll
    for (int k = 0; k < 32; k++) {
        float hv = g_h[n * 32 + k];
        c0 += hv * g_r2p[k * 2 + 0];
        c1 += hv * g_r2p[k * 2 + 1];
    }
    out[n * 2 + 0] = c0 + g_bp[0];
    out[n * 2 + 1] = c1 + g_bp[1];
}

extern "C" void kernel_launch(void* const* d_in, const int* in_sizes, int n_in,
                              void* d_out, int out_size) {
    const float* x     = (const float*)d_in[0];
    const void*  ei    = d_in[1];
    const void*  et    = d_in[2];
    const float* W1    = (const float*)d_in[3];
    const float* root1 = (const float*)d_in[4];
    const float* b1    = (const float*)d_in[5];
    const float* W2    = (const float*)d_in[6];
    const float* root2 = (const float*)d_in[7];
    const float* b2    = (const float*)d_in[8];
    const float* lin_w = (const float*)d_in[9];
    const float* lin_b = (const float*)d_in[10];
    float* out         = (float*)d_out;

    cudaFuncSetAttribute(gemm_f16_kernel,
                         cudaFuncAttributeMaxDynamicSharedMemorySize, GEMM_SMEM);

    detect_kernel<<<1, 32>>>((const int*)ei);
    prep_kernel<<<145, 256>>>(W1, root1, W2, root2, b2, lin_w, lin_b);
    zero_kernel<<<4096, 256>>>(x);
    pack_kernel<<<NE / 256, 256>>>(ei, et);
    gemm_f16_kernel<<<dim3((NN + GBM - 1) / GBM, NCOL / GBN), 256, GEMM_SMEM>>>();
    scatter1_kernel<<<(NE * 4) / 256, 256>>>();
    h_y2_kernel<<<NN / 32, 256>>>(b1);
    scatter2_kernel<<<NE / 256, 256>>>();
    out2_kernel<<<(NN + 255) / 256, 256>>>(out);
}